// round 15
// baseline (speedup 1.0000x reference)
#include <cuda_runtime.h>
#include <cuda_fp16.h>

#define BS    512
#define NN    256
#define NP2   128
#define ROWP  132                 // half2 per s_M row -> 528B stride
#define VROWP 68                  // half2 per s_V row -> 272B stride (16B aligned)
#define MAXIT 200
#define OMEGA 1.5f

// k_sor SMEM layout
#define OFF_M  0                               // 256*132*4 = 135168
#define OFF_V  135168                          // 2*128*68*4 = 69632
#define OFF_E  (OFF_V + 69632)                 // e_sm 1024
#define OFF_RS (OFF_E + 1024)                  // r_sm 1024
#define OFF_R  (OFF_RS + 1024)                 // red 32
#define SOR_SMEM (OFF_R + 64)

// k_inv SMEM layout
#define IOFF_V 0                               // sV fp32 [256][129] = 132096
#define IOFF_T 132096                          // T16 [2][128][128] half = 65536
#define IOFF_D (IOFF_T + 65536)                // sinv [256] fp32 = 1024
#define INV_SMEM (IOFF_D + 1024)

// 256*V for the two 128x128 diag-block inverses, fp16: [b][half][r][j]
__device__ __half g_V[(size_t)BS * 2 * 128 * 128];

__device__ __forceinline__ float warp_sum(float v) {
#pragma unroll
    for (int o = 16; o > 0; o >>= 1) v += __shfl_xor_sync(0xffffffffu, v, o);
    return v;
}

// FMA 16 fp16 coefs (uint4) against 8 e-values into 4 independent accs.
#define FOLD8(q, e0, e1, A0, A1, A2, A3)                                   \
    do {                                                                   \
        float2 f0 = __half22float2(*reinterpret_cast<__half2*>(&(q).x));   \
        float2 f1 = __half22float2(*reinterpret_cast<__half2*>(&(q).y));   \
        float2 f2 = __half22float2(*reinterpret_cast<__half2*>(&(q).z));   \
        float2 f3 = __half22float2(*reinterpret_cast<__half2*>(&(q).w));   \
        A0 = fmaf(-f0.x, (e0).x, A0); A1 = fmaf(-f0.y, (e0).y, A1);        \
        A2 = fmaf(-f1.x, (e0).z, A2); A3 = fmaf(-f1.y, (e0).w, A3);        \
        A0 = fmaf(-f2.x, (e1).x, A0); A1 = fmaf(-f2.y, (e1).y, A1);        \
        A2 = fmaf(-f3.x, (e1).z, A2); A3 = fmaf(-f3.y, (e1).w, A3);        \
    } while (0)

// Positive-sign variant (for V dot products).
#define PDOT8(q, e0, e1, A0, A1, A2, A3)                                   \
    do {                                                                   \
        float2 f0 = __half22float2(*reinterpret_cast<__half2*>(&(q).x));   \
        float2 f1 = __half22float2(*reinterpret_cast<__half2*>(&(q).y));   \
        float2 f2 = __half22float2(*reinterpret_cast<__half2*>(&(q).z));   \
        float2 f3 = __half22float2(*reinterpret_cast<__half2*>(&(q).w));   \
        A0 = fmaf(f0.x, (e0).x, A0); A1 = fmaf(f0.y, (e0).y, A1);          \
        A2 = fmaf(f1.x, (e0).z, A2); A3 = fmaf(f1.y, (e0).w, A3);          \
        A0 = fmaf(f2.x, (e1).x, A0); A1 = fmaf(f2.y, (e1).y, A1);          \
        A2 = fmaf(f3.x, (e1).z, A2); A3 = fmaf(f3.y, (e1).w, A3);          \
    } while (0)

// ---------------------------------------------------------------------------
// k_inv: per batch, invert the two 128x128 lower-tri diagonal blocks of
// T = D + wL. Thread = one row (independent backward recurrence):
//   V[r][r] = 1/d_r;  V[r][j] = -(sum_{k>j} V[r][k] T16[k][j]) / d_j.
// Zero-padded rows make the warp-uniform k-loop predicate-free. Warp w ->
// (half, block) mapped so SMSP pairs (w, w+4) get balanced block sizes.
// Stores 256*V as fp16 to g_V.
// ---------------------------------------------------------------------------
__global__ void __launch_bounds__(256) k_inv(const float* __restrict__ A) {
    extern __shared__ char sm[];
    float*  sV   = reinterpret_cast<float*>(sm + IOFF_V);   // [256][129]
    __half* sT   = reinterpret_cast<__half*>(sm + IOFF_T);  // [2][128][128]
    float*  sinv = reinterpret_cast<float*>(sm + IOFF_D);   // [256]
    int b = blockIdx.x, i = threadIdx.x, wid = i >> 5, lane = i & 31;
    const float* Ab = A + (size_t)b * NN * NN;

    int h   = wid >> 2;                        // half (0=top,1=bottom)
    int s   = wid & 3;
    int blk = h ? (3 - s) : s;                 // SMSP pair (s, 3-s): balanced
    int rl  = blk * 32 + lane;                 // row within half
    int g   = h * 128 + rl;                    // global row

    sinv[i] = 1.0f / Ab[(size_t)i * NN + i];
    float* Vr = sV + (size_t)g * 129;
    for (int k = 0; k < 129; k++) Vr[k] = 0.0f;
    for (int idx = i; idx < 2 * 128 * 128; idx += 256) {
        int hh = idx >> 14, rem = idx & 16383, rr = rem >> 7, jj = rem & 127;
        sT[idx] = __float2half(OMEGA * Ab[(size_t)(hh * 128 + rr) * NN + hh * 128 + jj]);
    }
    __syncthreads();

    float myinv = sinv[g];
    Vr[rl] = myinv;
    const __half* Th = sT + h * 16384;
    int kmax = blk * 32 + 31;
    float v_next = (rl == kmax) ? myinv : 0.0f;   // value at slot j+1
#pragma unroll 1
    for (int j = kmax - 1; j >= 0; j--) {
        float acc = __half2float(Th[(j + 1) * 128 + j]) * v_next;
#pragma unroll 4
        for (int k = j + 2; k <= kmax; k++)       // Vr[k]=0 beyond own row
            acc = fmaf(__half2float(Th[k * 128 + j]), Vr[k], acc);
        float val = -acc * sinv[h * 128 + j];
        if (j < rl) Vr[j] = val;
        v_next = (j == rl) ? myinv : ((j < rl) ? val : 0.0f);
    }
    __syncthreads();

    // write 256*V as fp16, coalesced in j
    for (int idx = i; idx < 2 * 128 * 128; idx += 256) {
        int hh = idx >> 14, rem = idx & 16383, rr = rem >> 7, jj = rem & 127;
        g_V[((size_t)(b * 2 + hh) * 128 + rr) * 128 + jj] =
            __float2half(256.0f * sV[(size_t)(hh * 128 + rr) * 129 + jj]);
    }
}

// ---------------------------------------------------------------------------
// k_sor: SMEM-resident iteration with 2-level block-inverse solve.
// Per sweep: A) r = ((1-w)D - wU)e   (all threads, parallel)
//            B) x_top = V0*r_top / 256   (threads 0-127)
//            C) acc = r_low - wL10*x_top (threads 128-255)
//            D) x_low = V1*acc / 256     (threads 128-255)
// Each batch iterates to its OWN convergence; tail zero-filled.
// ---------------------------------------------------------------------------
__global__ void __launch_bounds__(256) k_sor(const float* __restrict__ A,
                                             const float* __restrict__ xsol,
                                             const float* __restrict__ theta,
                                             const float* __restrict__ rtol,
                                             float* __restrict__ out) {
    extern __shared__ char smem_raw[];
    __half2* s_M  = reinterpret_cast<__half2*>(smem_raw + OFF_M);   // [256][132]
    __half2* s_V  = reinterpret_cast<__half2*>(smem_raw + OFF_V);   // [2*128][68]
    float*   e_sm = reinterpret_cast<float*>(smem_raw + OFF_E);
    float*   r_sm = reinterpret_cast<float*>(smem_raw + OFF_RS);
    float*   red  = reinterpret_cast<float*>(smem_raw + OFF_R);

    int b = blockIdx.x;
    int i = threadIdx.x, wid = i >> 5, lane = i & 31;
    const float* Ab   = A   + (size_t)b * NN * NN;
    float*       outb = out + (size_t)b * (MAXIT + 1);

    // ---- load wA into SMEM as fp16 rows (convert in flight) ----
    {
        int gg = i >> 7, c = i & 127;
        for (int r = 0; r < NN; r += 2) {
            int row = r + gg;
            float2 av = *reinterpret_cast<const float2*>(Ab + (size_t)row * NN + 2 * c);
            s_M[row * ROWP + c] = __floats2half2_rn(OMEGA * av.x, OMEGA * av.y);
        }
    }
    // ---- load V blocks ----
    {
        const __half2* gv = reinterpret_cast<const __half2*>(g_V) + (size_t)b * 2 * 128 * 64;
        for (int idx = i; idx < 2 * 128 * 64; idx += 256) {
            int r = idx >> 6, jp = idx & 63;   // r in [0,256): half*128+row
            s_V[r * VROWP + jp] = gv[idx];
        }
    }
    float dval = Ab[(size_t)i * NN + i];
    float dc   = (1.0f - OMEGA) * dval;

    // err0, xtol
    float xv = xsol[b * NN + i];
    float p = warp_sum(xv * xv);
    if (lane == 0) red[wid] = p;
    __syncthreads();
    float xtol = rtol[b] * sqrtf(red[0] + red[1] + red[2] + red[3] +
                                 red[4] + red[5] + red[6] + red[7]);
    __syncthreads();
    float e0 = theta[b * NN + i] - xv;
    e_sm[i] = e0;
    float q = warp_sum(e0 * e0);
    if (lane == 0) red[wid] = q;
    __syncthreads();
    float err = sqrtf(red[0] + red[1] + red[2] + red[3] +
                      red[4] + red[5] + red[6] + red[7]);
    if (i == 0) outb[0] = err;

    // pre-masked in-block upper coefficients (j>i within own 32-block)
    const __half2* Mi = s_M + i * ROWP;
    float uw[32];
#pragma unroll
    for (int m = 0; m < 16; m++) {
        float2 a = __half22float2(Mi[16 * wid + m]);
        int j0 = 32 * wid + 2 * m;
        uw[2 * m]     = (j0     > i) ? a.x : 0.0f;
        uw[2 * m + 1] = (j0 + 1 > i) ? a.y : 0.0f;
    }
    const uint4* Vrow = reinterpret_cast<const uint4*>(
        s_V + (size_t)((i < 128) ? i : i - 128 + 128) * VROWP);  // == row i
    __syncthreads();                           // s_M/s_V/e ready

    int t = 0;
    while (err > xtol && t < MAXIT) {          // err CTA-uniform
        t++;
        // ---- A: r = dc*e - wU e ----
        float a0 = dc * e_sm[i], a1 = 0.f, a2 = 0.f, a3 = 0.f;
        int jpb = 16 * wid + 16;
        const uint4* Mv = reinterpret_cast<const uint4*>(Mi + jpb);
        int nv = (NP2 - jpb) >> 2;
#pragma unroll 4
        for (int v = 0; v < nv; v++) {
            uint4 qd = Mv[v];
            float4 eA = *reinterpret_cast<const float4*>(&e_sm[2 * jpb + 8 * v]);
            float4 eB = *reinterpret_cast<const float4*>(&e_sm[2 * jpb + 8 * v + 4]);
            FOLD8(qd, eA, eB, a0, a1, a2, a3);
        }
        {
            const float4* eo = reinterpret_cast<const float4*>(&e_sm[32 * wid]);
#pragma unroll
            for (int m = 0; m < 8; m++) {
                float4 e4 = eo[m];
                a0 = fmaf(-uw[4 * m],     e4.x, a0);
                a1 = fmaf(-uw[4 * m + 1], e4.y, a1);
                a2 = fmaf(-uw[4 * m + 2], e4.z, a2);
                a3 = fmaf(-uw[4 * m + 3], e4.w, a3);
            }
        }
        r_sm[i] = (a0 + a1) + (a2 + a3);
        __syncthreads();

        // ---- B: x_top = V0 * r_top / 256 ----
        if (i < 128) {
            float b0 = 0.f, b1 = 0.f, b2 = 0.f, b3 = 0.f;
            const float4* rv = reinterpret_cast<const float4*>(r_sm);
#pragma unroll 4
            for (int v = 0; v < 16; v++) {
                uint4 qd = Vrow[v];
                float4 rA = rv[2 * v], rB = rv[2 * v + 1];
                PDOT8(qd, rA, rB, b0, b1, b2, b3);
            }
            float x = ((b0 + b1) + (b2 + b3)) * 0.00390625f;
            e_sm[i] = x;
            float pr = warp_sum(x * x);
            if (lane == 0) red[wid] = pr;
        }
        __syncthreads();

        // ---- C: acc = r_low - wL10 * x_top ----
        if (i >= 128) {
            float c0 = r_sm[i], c1 = 0.f, c2 = 0.f, c3 = 0.f;
            const uint4*  Lv = reinterpret_cast<const uint4*>(Mi);   // cols 0..127
            const float4* xv4 = reinterpret_cast<const float4*>(e_sm);
#pragma unroll 4
            for (int v = 0; v < 16; v++) {
                uint4 qd = Lv[v];
                float4 xA = xv4[2 * v], xB = xv4[2 * v + 1];
                FOLD8(qd, xA, xB, c0, c1, c2, c3);
            }
            r_sm[i] = (c0 + c1) + (c2 + c3);
        }
        __syncthreads();

        // ---- D: x_low = V1 * acc / 256 ----
        if (i >= 128) {
            float d0 = 0.f, d1 = 0.f, d2 = 0.f, d3 = 0.f;
            const float4* rv = reinterpret_cast<const float4*>(r_sm + 128);
#pragma unroll 4
            for (int v = 0; v < 16; v++) {
                uint4 qd = Vrow[v];
                float4 rA = rv[2 * v], rB = rv[2 * v + 1];
                PDOT8(qd, rA, rB, d0, d1, d2, d3);
            }
            float x = ((d0 + d1) + (d2 + d3)) * 0.00390625f;
            e_sm[i] = x;
            float pr = warp_sum(x * x);
            if (lane == 0) red[wid] = pr;
        }
        __syncthreads();

        err = sqrtf(red[0] + red[1] + red[2] + red[3] +
                    red[4] + red[5] + red[6] + red[7]);
        if (i == 0) outb[t] = err;
    }
    for (int t2 = t + 1 + i; t2 <= MAXIT; t2 += 256) outb[t2] = 0.0f;
}

extern "C" void kernel_launch(void* const* d_in, const int* in_sizes, int n_in,
                              void* d_out, int out_size) {
    const float* A     = (const float*)d_in[0];
    const float* xsol  = (const float*)d_in[2];
    const float* theta = (const float*)d_in[3];
    const float* rtol  = (const float*)d_in[4];
    float*       out   = (float*)d_out;

    static int attr_done = 0;                  // idempotent host-side attr set
    if (!attr_done) {
        cudaFuncSetAttribute(k_inv, cudaFuncAttributeMaxDynamicSharedMemorySize,
                             INV_SMEM);
        cudaFuncSetAttribute(k_sor, cudaFuncAttributeMaxDynamicSharedMemorySize,
                             SOR_SMEM);
        attr_done = 1;
    }
    k_inv<<<BS, 256, INV_SMEM>>>(A);
    k_sor<<<BS, 256, SOR_SMEM>>>(A, xsol, theta, rtol, out);
}

// round 16
// speedup vs baseline: 1.6690x; 1.6690x over previous
#include <cuda_runtime.h>
#include <cuda_fp16.h>

#define BS    512
#define NN    256
#define NP2   128
#define ROWP  132                 // half2 per s_M row -> 528B stride
#define VROWP 68                  // half2 per s_V row -> 272B stride (16B aligned)
#define MAXIT 200
#define OMEGA 1.5f

// k_sor SMEM layout (unchanged from R15)
#define OFF_M  0                               // 256*132*4 = 135168
#define OFF_V  135168                          // 2*128*68*4 = 69632
#define OFF_E  (OFF_V + 69632)                 // e_sm 1024
#define OFF_RS (OFF_E + 1024)                  // r_sm 1024
#define OFF_R  (OFF_RS + 1024)                 // red 32
#define SOR_SMEM (OFF_R + 64)

// k_inv v2 SMEM layout (78 KB -> 2 CTAs/SM)
#define I2_SY   0                              // sY fp16 [256][132] = 67584
#define I2_SHL  67584                          // shL fp32 [2][32][36] = 9216
#define I2_SINV (I2_SHL + 9216)                // sinv [256] fp32 = 1024
#define INV_SMEM (I2_SINV + 1024)              // 77824

// 256*V for the two 128x128 diag-block inverses, fp16: [b][half][r][j]
__device__ __half g_V[(size_t)BS * 2 * 128 * 128];

__device__ __forceinline__ float warp_sum(float v) {
#pragma unroll
    for (int o = 16; o > 0; o >>= 1) v += __shfl_xor_sync(0xffffffffu, v, o);
    return v;
}

// FMA 16 fp16 coefs (uint4) against 8 e-values into 4 independent accs.
#define FOLD8(q, e0, e1, A0, A1, A2, A3)                                   \
    do {                                                                   \
        float2 f0 = __half22float2(*reinterpret_cast<__half2*>(&(q).x));   \
        float2 f1 = __half22float2(*reinterpret_cast<__half2*>(&(q).y));   \
        float2 f2 = __half22float2(*reinterpret_cast<__half2*>(&(q).z));   \
        float2 f3 = __half22float2(*reinterpret_cast<__half2*>(&(q).w));   \
        A0 = fmaf(-f0.x, (e0).x, A0); A1 = fmaf(-f0.y, (e0).y, A1);        \
        A2 = fmaf(-f1.x, (e0).z, A2); A3 = fmaf(-f1.y, (e0).w, A3);        \
        A0 = fmaf(-f2.x, (e1).x, A0); A1 = fmaf(-f2.y, (e1).y, A1);        \
        A2 = fmaf(-f3.x, (e1).z, A2); A3 = fmaf(-f3.y, (e1).w, A3);        \
    } while (0)

// Positive-sign variant (for V dot products).
#define PDOT8(q, e0, e1, A0, A1, A2, A3)                                   \
    do {                                                                   \
        float2 f0 = __half22float2(*reinterpret_cast<__half2*>(&(q).x));   \
        float2 f1 = __half22float2(*reinterpret_cast<__half2*>(&(q).y));   \
        float2 f2 = __half22float2(*reinterpret_cast<__half2*>(&(q).z));   \
        float2 f3 = __half22float2(*reinterpret_cast<__half2*>(&(q).w));   \
        A0 = fmaf(f0.x, (e0).x, A0); A1 = fmaf(f0.y, (e0).y, A1);          \
        A2 = fmaf(f1.x, (e0).z, A2); A3 = fmaf(f1.y, (e0).w, A3);          \
        A0 = fmaf(f2.x, (e1).x, A0); A1 = fmaf(f2.y, (e1).y, A1);          \
        A2 = fmaf(f3.x, (e1).z, A2); A3 = fmaf(f3.y, (e1).w, A3);          \
    } while (0)

// ---------------------------------------------------------------------------
// k_inv v2: column-parallel blocked forward substitution.
// Thread = (half h, column c): solves T_h z = 256 e_c over 4 row-blocks of 32
// with acc[32] registers and cooperative fp32 tiles (1 LDS.128 per 4 FMA).
// Column sparsity (z_r = 0 for r < c) prunes tiles/blocks per warp; warp->q
// map pairs heavy and empty column-blocks on each SMSP.
// Stores 256*V[r][c] fp16 to g_V (rows r < c written as 0).
// ---------------------------------------------------------------------------
__global__ void __launch_bounds__(256) k_inv(const float* __restrict__ A) {
    extern __shared__ char sm[];
    __half* sY   = reinterpret_cast<__half*>(sm + I2_SY);    // [t][132] own col
    float*  shL  = reinterpret_cast<float*>(sm + I2_SHL);    // [2][32][36]
    float*  sinv = reinterpret_cast<float*>(sm + I2_SINV);   // [256]
    int b = blockIdx.x, t = threadIdx.x;
    int wid = t >> 5, lane = t & 31, h = t >> 7, tl = t & 127;
    int q = (h == 0) ? (wid & 3) : (3 - (wid & 3));          // SMSP balance
    int c = q * 32 + lane;                                   // own column
    const float* Ab = A + (size_t)b * NN * NN;

    sinv[t] = 1.0f / Ab[(size_t)t * NN + t];
    __syncthreads();
    float* shLh = shL + h * (32 * 36);

#pragma unroll 1
    for (int blk = 0; blk < 4; blk++) {
        int r0 = blk * 32;
        float acc[32];
#pragma unroll
        for (int k = 0; k < 32; k++) acc[k] = (r0 + k == c) ? 256.0f : 0.0f;

        // Left-looking update tiles (cooperative load; FMA only if z != 0).
#pragma unroll 1
        for (int j0 = 0; j0 < r0; j0 += 32) {
            __syncthreads();                   // previous tile fully consumed
            for (int e = tl; e < 1024; e += 128) {
                int k = e >> 5, jj = e & 31;
                shLh[k * 36 + jj] =
                    OMEGA * Ab[(size_t)(h * 128 + r0 + k) * NN + h * 128 + j0 + jj];
            }
            __syncthreads();
            if (blk > q && j0 >= q * 32) {     // warp-uniform
                float yv[32];
#pragma unroll
                for (int jj = 0; jj < 32; jj++)
                    yv[jj] = __half2float(sY[t * 132 + j0 + jj]);
#pragma unroll
                for (int jj4 = 0; jj4 < 32; jj4 += 4) {
#pragma unroll
                    for (int k = 0; k < 32; k++) {
                        float4 a = *reinterpret_cast<const float4*>(&shLh[k * 36 + jj4]);
                        acc[k] = fmaf(-a.x, yv[jj4],     acc[k]);
                        acc[k] = fmaf(-a.y, yv[jj4 + 1], acc[k]);
                        acc[k] = fmaf(-a.z, yv[jj4 + 2], acc[k]);
                        acc[k] = fmaf(-a.w, yv[jj4 + 3], acc[k]);
                    }
                }
            }
        }

        // Diagonal tile + serial 32x32 solve (or zero rows for blk < q).
        __syncthreads();
        for (int e = tl; e < 1024; e += 128) {
            int k = e >> 5, jj = e & 31;
            shLh[k * 36 + jj] =
                OMEGA * Ab[(size_t)(h * 128 + r0 + k) * NN + h * 128 + r0 + jj];
        }
        __syncthreads();
        if (blk >= q) {                        // warp-uniform
#pragma unroll
            for (int k = 0; k < 32; k++) {
                float zk = acc[k] * sinv[h * 128 + r0 + k];
                sY[t * 132 + r0 + k] = __float2half(zk);
                g_V[((size_t)(b * 2 + h) * 128 + r0 + k) * 128 + c] = __float2half(zk);
#pragma unroll
                for (int m = k + 1; m < 32; m++)
                    acc[m] = fmaf(-shLh[m * 36 + k], zk, acc[m]);
            }
        } else {
#pragma unroll
            for (int k = 0; k < 32; k++)
                g_V[((size_t)(b * 2 + h) * 128 + r0 + k) * 128 + c] = __float2half(0.0f);
        }
    }
}

// ---------------------------------------------------------------------------
// k_sor: SMEM-resident iteration with 2-level block-inverse solve (R15).
// Per sweep: A) r = ((1-w)D - wU)e   (all threads, parallel)
//            B) x_top = V0*r_top / 256   (threads 0-127)
//            C) acc = r_low - wL10*x_top (threads 128-255)
//            D) x_low = V1*acc / 256     (threads 128-255)
// Each batch iterates to its OWN convergence; tail zero-filled.
// ---------------------------------------------------------------------------
__global__ void __launch_bounds__(256) k_sor(const float* __restrict__ A,
                                             const float* __restrict__ xsol,
                                             const float* __restrict__ theta,
                                             const float* __restrict__ rtol,
                                             float* __restrict__ out) {
    extern __shared__ char smem_raw[];
    __half2* s_M  = reinterpret_cast<__half2*>(smem_raw + OFF_M);   // [256][132]
    __half2* s_V  = reinterpret_cast<__half2*>(smem_raw + OFF_V);   // [2*128][68]
    float*   e_sm = reinterpret_cast<float*>(smem_raw + OFF_E);
    float*   r_sm = reinterpret_cast<float*>(smem_raw + OFF_RS);
    float*   red  = reinterpret_cast<float*>(smem_raw + OFF_R);

    int b = blockIdx.x;
    int i = threadIdx.x, wid = i >> 5, lane = i & 31;
    const float* Ab   = A   + (size_t)b * NN * NN;
    float*       outb = out + (size_t)b * (MAXIT + 1);

    // ---- load wA into SMEM as fp16 rows (convert in flight) ----
    {
        int gg = i >> 7, c = i & 127;
        for (int r = 0; r < NN; r += 2) {
            int row = r + gg;
            float2 av = *reinterpret_cast<const float2*>(Ab + (size_t)row * NN + 2 * c);
            s_M[row * ROWP + c] = __floats2half2_rn(OMEGA * av.x, OMEGA * av.y);
        }
    }
    // ---- load V blocks ----
    {
        const __half2* gv = reinterpret_cast<const __half2*>(g_V) + (size_t)b * 2 * 128 * 64;
        for (int idx = i; idx < 2 * 128 * 64; idx += 256) {
            int r = idx >> 6, jp = idx & 63;
            s_V[r * VROWP + jp] = gv[idx];
        }
    }
    float dval = Ab[(size_t)i * NN + i];
    float dc   = (1.0f - OMEGA) * dval;

    // err0, xtol
    float xv = xsol[b * NN + i];
    float p = warp_sum(xv * xv);
    if (lane == 0) red[wid] = p;
    __syncthreads();
    float xtol = rtol[b] * sqrtf(red[0] + red[1] + red[2] + red[3] +
                                 red[4] + red[5] + red[6] + red[7]);
    __syncthreads();
    float e0 = theta[b * NN + i] - xv;
    e_sm[i] = e0;
    float q = warp_sum(e0 * e0);
    if (lane == 0) red[wid] = q;
    __syncthreads();
    float err = sqrtf(red[0] + red[1] + red[2] + red[3] +
                      red[4] + red[5] + red[6] + red[7]);
    if (i == 0) outb[0] = err;

    // pre-masked in-block upper coefficients (j>i within own 32-block)
    const __half2* Mi = s_M + i * ROWP;
    float uw[32];
#pragma unroll
    for (int m = 0; m < 16; m++) {
        float2 a = __half22float2(Mi[16 * wid + m]);
        int j0 = 32 * wid + 2 * m;
        uw[2 * m]     = (j0     > i) ? a.x : 0.0f;
        uw[2 * m + 1] = (j0 + 1 > i) ? a.y : 0.0f;
    }
    const uint4* Vrow = reinterpret_cast<const uint4*>(
        s_V + (size_t)i * VROWP);              // row i (halves stacked)
    __syncthreads();                           // s_M/s_V/e ready

    int t = 0;
    while (err > xtol && t < MAXIT) {          // err CTA-uniform
        t++;
        // ---- A: r = dc*e - wU e ----
        float a0 = dc * e_sm[i], a1 = 0.f, a2 = 0.f, a3 = 0.f;
        int jpb = 16 * wid + 16;
        const uint4* Mv = reinterpret_cast<const uint4*>(Mi + jpb);
        int nv = (NP2 - jpb) >> 2;
#pragma unroll 4
        for (int v = 0; v < nv; v++) {
            uint4 qd = Mv[v];
            float4 eA = *reinterpret_cast<const float4*>(&e_sm[2 * jpb + 8 * v]);
            float4 eB = *reinterpret_cast<const float4*>(&e_sm[2 * jpb + 8 * v + 4]);
            FOLD8(qd, eA, eB, a0, a1, a2, a3);
        }
        {
            const float4* eo = reinterpret_cast<const float4*>(&e_sm[32 * wid]);
#pragma unroll
            for (int m = 0; m < 8; m++) {
                float4 e4 = eo[m];
                a0 = fmaf(-uw[4 * m],     e4.x, a0);
                a1 = fmaf(-uw[4 * m + 1], e4.y, a1);
                a2 = fmaf(-uw[4 * m + 2], e4.z, a2);
                a3 = fmaf(-uw[4 * m + 3], e4.w, a3);
            }
        }
        r_sm[i] = (a0 + a1) + (a2 + a3);
        __syncthreads();

        // ---- B: x_top = V0 * r_top / 256 ----
        if (i < 128) {
            float b0 = 0.f, b1 = 0.f, b2 = 0.f, b3 = 0.f;
            const float4* rv = reinterpret_cast<const float4*>(r_sm);
#pragma unroll 4
            for (int v = 0; v < 16; v++) {
                uint4 qd = Vrow[v];
                float4 rA = rv[2 * v], rB = rv[2 * v + 1];
                PDOT8(qd, rA, rB, b0, b1, b2, b3);
            }
            float x = ((b0 + b1) + (b2 + b3)) * 0.00390625f;
            e_sm[i] = x;
            float pr = warp_sum(x * x);
            if (lane == 0) red[wid] = pr;
        }
        __syncthreads();

        // ---- C: acc = r_low - wL10 * x_top ----
        if (i >= 128) {
            float c0 = r_sm[i], c1 = 0.f, c2 = 0.f, c3 = 0.f;
            const uint4*  Lv  = reinterpret_cast<const uint4*>(Mi);
            const float4* xv4 = reinterpret_cast<const float4*>(e_sm);
#pragma unroll 4
            for (int v = 0; v < 16; v++) {
                uint4 qd = Lv[v];
                float4 xA = xv4[2 * v], xB = xv4[2 * v + 1];
                FOLD8(qd, xA, xB, c0, c1, c2, c3);
            }
            r_sm[i] = (c0 + c1) + (c2 + c3);
        }
        __syncthreads();

        // ---- D: x_low = V1 * acc / 256 ----
        if (i >= 128) {
            float d0 = 0.f, d1 = 0.f, d2 = 0.f, d3 = 0.f;
            const float4* rv = reinterpret_cast<const float4*>(r_sm + 128);
#pragma unroll 4
            for (int v = 0; v < 16; v++) {
                uint4 qd = Vrow[v];
                float4 rA = rv[2 * v], rB = rv[2 * v + 1];
                PDOT8(qd, rA, rB, d0, d1, d2, d3);
            }
            float x = ((d0 + d1) + (d2 + d3)) * 0.00390625f;
            e_sm[i] = x;
            float pr = warp_sum(x * x);
            if (lane == 0) red[wid] = pr;
        }
        __syncthreads();

        err = sqrtf(red[0] + red[1] + red[2] + red[3] +
                    red[4] + red[5] + red[6] + red[7]);
        if (i == 0) outb[t] = err;
    }
    for (int t2 = t + 1 + i; t2 <= MAXIT; t2 += 256) outb[t2] = 0.0f;
}

extern "C" void kernel_launch(void* const* d_in, const int* in_sizes, int n_in,
                              void* d_out, int out_size) {
    const float* A     = (const float*)d_in[0];
    const float* xsol  = (const float*)d_in[2];
    const float* theta = (const float*)d_in[3];
    const float* rtol  = (const float*)d_in[4];
    float*       out   = (float*)d_out;

    static int attr_done = 0;                  // idempotent host-side attr set
    if (!attr_done) {
        cudaFuncSetAttribute(k_inv, cudaFuncAttributeMaxDynamicSharedMemorySize,
                             INV_SMEM);
        cudaFuncSetAttribute(k_sor, cudaFuncAttributeMaxDynamicSharedMemorySize,
                             SOR_SMEM);
        attr_done = 1;
    }
    k_inv<<<BS, 256, INV_SMEM>>>(A);
    k_sor<<<BS, 256, SOR_SMEM>>>(A, xsol, theta, rtol, out);
}